// round 16
// baseline (speedup 1.0000x reference)
#include <cuda_runtime.h>
#include <cuda_fp16.h>
#include <math.h>

#define BQ   512
#define TQ   1024
#define DQ   4
#define HQ   64
#define G4   256          // 4*H
#define NB   4            // batches per recurrent block (2 blocks/SM, paired)
#define NCLS 1098
#define FB   4            // batches per final-head block

#define HXH_STRIDE 88     // halves; conflict-free B-frag LDS (audited)

// ---------------- scratch (static device allocations only) ----------------
__device__ float  g_g1[2][(size_t)BQ * TQ * G4];  // layer-1 gate preactivations per dir
__device__ __half g_h0[(size_t)BQ * TQ * 128];    // layer-0 bidir output (fp16)
__device__ float  g_h1last[BQ * 128];             // gathered last timestep of layer 1

// ---------------- helpers ----------------
__device__ __forceinline__ float tanh_fast(float x) {
    float y; asm("tanh.approx.f32 %0,%1;" : "=f"(y) : "f"(x)); return y;
}
__device__ __forceinline__ float sig_fast(float x) {
    return fmaf(0.5f, tanh_fast(0.5f * x), 0.5f);
}
__device__ __forceinline__ unsigned pack_h2(float lo, float hi) {
    __half2 h = __floats2half2_rn(lo, hi);
    return *reinterpret_cast<unsigned*>(&h);
}
// fp16 MMA, fp32 accumulate
__device__ __forceinline__ void mma_f16(float* c, const unsigned* a, unsigned b0, unsigned b1) {
    asm volatile(
        "mma.sync.aligned.m16n8k16.row.col.f32.f16.f16.f32 "
        "{%0,%1,%2,%3},{%4,%5,%6,%7},{%8,%9},{%0,%1,%2,%3};"
        : "+f"(c[0]), "+f"(c[1]), "+f"(c[2]), "+f"(c[3])
        : "r"(a[0]), "r"(a[1]), "r"(a[2]), "r"(a[3]), "r"(b0), "r"(b1));
}

// block (0..255) -> sorted group id: pairs wave-1 co-resident blocks
// (bid, bid+148) with (long, short) sequence groups.
__device__ __forceinline__ void block_to_group(int bid, int& dir, int& xb) {
    int j = (bid < 148) ? bid : (403 - bid);
    dir = j & 1;
    xb  = j >> 1;
}

// =====================================================================
// Layer 0: bidirectional LSTM; fp16 tensor-core matvec with
// GATE-REMAPPED fragments + warp-shuffle gate exchange.
//   A reg e (tile mt): gate = (mt*2 + (e&1))*64 + (8w + gid)
//   => lane (gid,tig) holds i,f (tile0) & g,o (tile1) of unit 8w+gid
//      for batches 2tig, 2tig+1 (cols 0..3 real at NB=4).
// Exchange: lane l = (bt<<3)|(u&7) pulls its 4 gates from lane
//   src=(l&7)*4+(bt>>1), element bt&1 -> in-warp pointwise, ZERO waste.
// hx double-buffered => ONE __syncthreads per step, no gpre smem.
// =====================================================================
__global__ void __launch_bounds__(256, 2)
lstm_l0_kernel(const float* __restrict__ x, const int* __restrict__ lens,
               const float* __restrict__ WihF, const float* __restrict__ WhhF,
               const float* __restrict__ bihF, const float* __restrict__ bhhF,
               const float* __restrict__ WihB, const float* __restrict__ WhhB,
               const float* __restrict__ bihB, const float* __restrict__ bhhB)
{
    int dir, xb;
    block_to_group(blockIdx.x, dir, xb);
    const int bbase = xb * NB;
    const int tid  = threadIdx.x;
    const int w    = tid >> 5;
    const int lane = tid & 31;
    const int gid  = lane >> 2;               // 0..7 (frag row grp / B column)
    const int tig  = lane & 3;                // 0..3
    const int u    = w * 8 + gid;             // fragment unit
    const int bt   = lane >> 3;               // phase-B batch 0..3
    const int uo   = w * 8 + (lane & 7);      // phase-B unit
    const int src  = (lane & 7) * 4 + (bt >> 1);
    const bool hi  = (bt & 1) != 0;

    const float* Wih = dir ? WihB : WihF;
    const float* Whh = dir ? WhhB : WhhF;
    const float* bih = dir ? bihB : bihF;
    const float* bhh = dir ? bhhB : bhhF;

    // ---- A fragments (fp16), gate-remapped rows, K = 80 augmented
    unsigned afr[2][5][4];
#pragma unroll
    for (int mt = 0; mt < 2; ++mt) {
#pragma unroll
        for (int kc = 0; kc < 5; ++kc) {
#pragma unroll
            for (int e = 0; e < 4; ++e) {
                int g  = (mt * 2 + (e & 1)) * 64 + u;   // i/f (mt0), g/o (mt1)
                int kb = kc * 16 + 2 * tig + ((e & 2) ? 8 : 0);
                float v0, v1;
                {
                    int k = kb;
                    v0 = (k < 64) ? Whh[g * HQ + k]
                       : (k < 68) ? Wih[g * DQ + (k - 64)]
                       : (k == 68) ? (bih[g] + bhh[g]) : 0.0f;
                }
                {
                    int k = kb + 1;
                    v1 = (k < 64) ? Whh[g * HQ + k]
                       : (k < 68) ? Wih[g * DQ + (k - 64)]
                       : (k == 68) ? (bih[g] + bhh[g]) : 0.0f;
                }
                afr[mt][kc][e] = pack_h2(v0, v1);
            }
        }
    }

    __shared__ __half hx[2][8][HXH_STRIDE];
    __shared__ int    lsh[NB];

    if (tid < NB) lsh[tid] = lens[bbase + tid];
    for (int i = tid; i < 2 * 8 * HXH_STRIDE; i += 256)
        (&hx[0][0][0])[i] = __float2half(0.0f);
    __syncthreads();
    if (tid < 2 * NB) hx[tid >> 2][tid & 3][68] = __float2half(1.0f);  // bias lane

    const int maxlen = lsh[0];                // lens sorted descending
    const int mylen  = lsh[bt];
    float c = 0.0f;

    if (tid < NB) {
        int len = lsh[tid];
        int tt  = dir ? (len - 1) : 0;
        float4 xv = reinterpret_cast<const float4*>(x)[(size_t)(bbase + tid) * TQ + tt];
        hx[0][tid][64] = __float2half(xv.x); hx[0][tid][65] = __float2half(xv.y);
        hx[0][tid][66] = __float2half(xv.z); hx[0][tid][67] = __float2half(xv.w);
    }
    __syncthreads();

    for (int t = 0; t < maxlen; ++t) {
        const int buf = t & 1, nbuf = buf ^ 1;

        // prefetch x(t+1) (overlaps MMA)
        float4 xn = make_float4(0.f, 0.f, 0.f, 0.f);
        if (tid < NB) {
            int tn  = (t + 1 < maxlen) ? (t + 1) : t;
            int len = lsh[tid];
            int tt  = dir ? ((tn < len) ? (len - 1 - tn) : tn) : tn;
            xn = reinterpret_cast<const float4*>(x)[(size_t)(bbase + tid) * TQ + tt];
        }

        // ---- phase A: fp16 tensor-core matvec (5 K-chunks, 2 tiles)
        const __half* hxb = &hx[buf][gid][0];
        float a0[4] = {0.f, 0.f, 0.f, 0.f}, a1[4] = {0.f, 0.f, 0.f, 0.f};
#pragma unroll
        for (int kc = 0; kc < 5; ++kc) {
            unsigned p = *reinterpret_cast<const unsigned*>(&hxb[kc * 16 + 2 * tig]);
            unsigned q = *reinterpret_cast<const unsigned*>(&hxb[kc * 16 + 2 * tig + 8]);
            mma_f16(a0, afr[0][kc], p, q);
            mma_f16(a1, afr[1][kc], p, q);
        }

        // ---- gate exchange via warp shuffles (no smem, no extra barrier)
        float i_lo = __shfl_sync(0xffffffffu, a0[0], src);
        float i_hi = __shfl_sync(0xffffffffu, a0[1], src);
        float f_lo = __shfl_sync(0xffffffffu, a0[2], src);
        float f_hi = __shfl_sync(0xffffffffu, a0[3], src);
        float g_lo = __shfl_sync(0xffffffffu, a1[0], src);
        float g_hi = __shfl_sync(0xffffffffu, a1[1], src);
        float o_lo = __shfl_sync(0xffffffffu, a1[2], src);
        float o_hi = __shfl_sync(0xffffffffu, a1[3], src);
        float gi = hi ? i_hi : i_lo;
        float gf = hi ? f_hi : f_lo;
        float gc = hi ? g_hi : g_lo;
        float go = hi ? o_hi : o_lo;

        // ---- phase B: in-warp pointwise for (bt, uo)
        {
            float si = sig_fast(gi);
            float sf = sig_fast(gf);
            float tg = tanh_fast(gc);
            float so = sig_fast(go);
            c = sf * c + si * tg;
            float h = so * tanh_fast(c);
            __half hh = __float2half_rn(h);
            hx[nbuf][bt][uo] = hh;

            int ts = dir ? ((t < mylen) ? (mylen - 1 - t) : t) : t;
            g_h0[((size_t)(bbase + bt) * TQ + ts) * 128 + dir * HQ + uo] = hh;
        }
        if (tid < NB) {
            hx[nbuf][tid][64] = __float2half(xn.x);
            hx[nbuf][tid][65] = __float2half(xn.y);
            hx[nbuf][tid][66] = __float2half(xn.z);
            hx[nbuf][tid][67] = __float2half(xn.w);
        }
        __syncthreads();
    }
}

// =====================================================================
// Layer-1 gate GEMM on fp16 tensor cores (R13, unchanged).
// =====================================================================
#define GM_ROWS   64
#define ASH_STRIDE 136
#define WSH_STRIDE 136
#define GEMM_SMEM ((GM_ROWS * ASH_STRIDE + G4 * WSH_STRIDE) * 2)   // 87040 B

__global__ void __launch_bounds__(256, 2)
gates1_gemm_kernel(const int* __restrict__ lens,
                   const float* __restrict__ WihF, const float* __restrict__ WihB,
                   const float* __restrict__ bihF, const float* __restrict__ bhhF,
                   const float* __restrict__ bihB, const float* __restrict__ bhhB)
{
    const int tile  = blockIdx.x;
    const int b     = blockIdx.y;
    const int dir   = blockIdx.z;
    const int tbase = tile * GM_ROWS;

    const int len = lens[b];
    if (tbase >= len) return;

    extern __shared__ __half smh[];
    __half* As = smh;
    __half* Ws = smh + GM_ROWS * ASH_STRIDE;

    const int tid  = threadIdx.x;
    const int lane = tid & 31;
    const int w    = tid >> 5;
    const int wr   = w & 3;
    const int wc   = w >> 2;
    const int gid  = lane >> 2;
    const int tig  = lane & 3;

    const float* Wih = dir ? WihB : WihF;
    const float* bih = dir ? bihB : bihF;
    const float* bhh = dir ? bhhB : bhhF;

    float acc[16][4];
#pragma unroll
    for (int nt = 0; nt < 16; ++nt) {
        int col0 = wc * 128 + nt * 8 + 2 * tig;
        float bv0 = bih[col0]     + bhh[col0];
        float bv1 = bih[col0 + 1] + bhh[col0 + 1];
        acc[nt][0] = bv0; acc[nt][1] = bv1;
        acc[nt][2] = bv0; acc[nt][3] = bv1;
    }

    const __half* h0b = g_h0 + (size_t)b * TQ * 128;
#pragma unroll
    for (int i = 0; i < 4; ++i) {
        int idx = tid + 256 * i;
        int r   = idx >> 4, kq = idx & 15;
        int srow = tbase + r;
        if (dir) srow = (srow < len) ? (len - 1 - srow) : srow;
        uint4 v = *reinterpret_cast<const uint4*>(h0b + (size_t)srow * 128 + 8 * kq);
        *reinterpret_cast<uint4*>(&As[r * ASH_STRIDE + 8 * kq]) = v;
    }

#pragma unroll
    for (int i = 0; i < 32; ++i) {
        int idx = tid + 256 * i;
        int n   = idx >> 5, kq = idx & 31;
        float4 v = *reinterpret_cast<const float4*>(Wih + (size_t)n * 128 + 4 * kq);
        __half2 lo = __floats2half2_rn(v.x, v.y);
        __half2 hi = __floats2half2_rn(v.z, v.w);
        *reinterpret_cast<__half2*>(&Ws[n * WSH_STRIDE + 4 * kq])     = lo;
        *reinterpret_cast<__half2*>(&Ws[n * WSH_STRIDE + 4 * kq + 2]) = hi;
    }
    __syncthreads();

    const int r0 = wr * 16 + gid;

#pragma unroll
    for (int kc = 0; kc < 8; ++kc) {
        const int kl = kc * 16;
        unsigned a[4];
        a[0] = *reinterpret_cast<const unsigned*>(&As[r0 * ASH_STRIDE + kl + 2 * tig]);
        a[1] = *reinterpret_cast<const unsigned*>(&As[(r0 + 8) * ASH_STRIDE + kl + 2 * tig]);
        a[2] = *reinterpret_cast<const unsigned*>(&As[r0 * ASH_STRIDE + kl + 2 * tig + 8]);
        a[3] = *reinterpret_cast<const unsigned*>(&As[(r0 + 8) * ASH_STRIDE + kl + 2 * tig + 8]);
#pragma unroll
        for (int nt = 0; nt < 16; ++nt) {
            int n = wc * 128 + nt * 8 + gid;
            unsigned b0 = *reinterpret_cast<const unsigned*>(&Ws[n * WSH_STRIDE + kl + 2 * tig]);
            unsigned b1 = *reinterpret_cast<const unsigned*>(&Ws[n * WSH_STRIDE + kl + 2 * tig + 8]);
            mma_f16(acc[nt], a, b0, b1);
        }
    }

    float* outp = g_g1[dir] + ((size_t)b * TQ + tbase) * G4;
#pragma unroll
    for (int nt = 0; nt < 16; ++nt) {
        int col0 = wc * 128 + nt * 8 + 2 * tig;
        *reinterpret_cast<float2*>(outp + (size_t)r0 * G4 + col0) =
            make_float2(acc[nt][0], acc[nt][1]);
        *reinterpret_cast<float2*>(outp + (size_t)(r0 + 8) * G4 + col0) =
            make_float2(acc[nt][2], acc[nt][3]);
    }
}

// =====================================================================
// Layer 1: recurrent over precomputed gates; fp16 MMA (K=64),
// gate-remapped fragments + warp-shuffle exchange, ONE barrier/step.
// Preacts streamed per (bt, uo) lane role, added after the shuffle.
// =====================================================================
__global__ void __launch_bounds__(256, 2)
lstm_l1_kernel(const int* __restrict__ lens,
               const float* __restrict__ WhhF, const float* __restrict__ WhhB)
{
    int dir, xb;
    block_to_group(blockIdx.x, dir, xb);
    const int bbase = xb * NB;
    const int tid  = threadIdx.x;
    const int w    = tid >> 5;
    const int lane = tid & 31;
    const int gid  = lane >> 2;
    const int tig  = lane & 3;
    const int u    = w * 8 + gid;
    const int bt   = lane >> 3;
    const int uo   = w * 8 + (lane & 7);
    const int src  = (lane & 7) * 4 + (bt >> 1);
    const bool hi  = (bt & 1) != 0;

    const float* Whh = dir ? WhhB : WhhF;
    const float* gin = g_g1[dir];

    // ---- A fragments (fp16), gate-remapped rows, K = 64
    unsigned afr[2][4][4];
#pragma unroll
    for (int mt = 0; mt < 2; ++mt) {
#pragma unroll
        for (int kc = 0; kc < 4; ++kc) {
#pragma unroll
            for (int e = 0; e < 4; ++e) {
                int g  = (mt * 2 + (e & 1)) * 64 + u;
                int kb = kc * 16 + 2 * tig + ((e & 2) ? 8 : 0);
                afr[mt][kc][e] = pack_h2(Whh[g * HQ + kb], Whh[g * HQ + kb + 1]);
            }
        }
    }

    __shared__ __half hx[2][8][HXH_STRIDE];
    __shared__ int    lsh[NB];

    if (tid < NB) lsh[tid] = lens[bbase + tid];
    for (int i = tid; i < 2 * 8 * HXH_STRIDE; i += 256)
        (&hx[0][0][0])[i] = __float2half(0.0f);
    float c = 0.0f;
    __syncthreads();

    const int maxlen = lsh[0];
    const int mylen  = lsh[bt];

    // per-lane preact stream for (bt, uo)
    const float* gsrc = gin + (size_t)(bbase + bt) * TQ * G4 + uo;

    float ldc[4];
#pragma unroll
    for (int q = 0; q < 4; ++q) ldc[q] = gsrc[q * 64];

    for (int t = 0; t < maxlen; ++t) {
        const int buf = t & 1, nbuf = buf ^ 1;

        // prefetch next-step preacts (overlaps MMA)
        float ldn[4];
        const int tn = (t + 1 < maxlen) ? (t + 1) : t;
#pragma unroll
        for (int q = 0; q < 4; ++q) ldn[q] = gsrc[(size_t)tn * G4 + q * 64];

        // ---- phase A: fp16 tensor-core matvec (4 K-chunks, 2 tiles)
        const __half* hxb = &hx[buf][gid][0];
        float a0[4] = {0.f, 0.f, 0.f, 0.f}, a1[4] = {0.f, 0.f, 0.f, 0.f};
#pragma unroll
        for (int kc = 0; kc < 4; ++kc) {
            unsigned p = *reinterpret_cast<const unsigned*>(&hxb[kc * 16 + 2 * tig]);
            unsigned q = *reinterpret_cast<const unsigned*>(&hxb[kc * 16 + 2 * tig + 8]);
            mma_f16(a0, afr[0][kc], p, q);
            mma_f16(a1, afr[1][kc], p, q);
        }

        // ---- gate exchange via warp shuffles
        float i_lo = __shfl_sync(0xffffffffu, a0[0], src);
        float i_hi = __shfl_sync(0xffffffffu, a0[1], src);
        float f_lo = __shfl_sync(0xffffffffu, a0[2], src);
        float f_hi = __shfl_sync(0xffffffffu, a0[3], src);
        float g_lo = __shfl_sync(0xffffffffu, a1[0], src);
        float g_hi = __shfl_sync(0xffffffffu, a1[1], src);
        float o_lo = __shfl_sync(0xffffffffu, a1[2], src);
        float o_hi = __shfl_sync(0xffffffffu, a1[3], src);
        float gi = (hi ? i_hi : i_lo) + ldc[0];
        float gf = (hi ? f_hi : f_lo) + ldc[1];
        float gc = (hi ? g_hi : g_lo) + ldc[2];
        float go = (hi ? o_hi : o_lo) + ldc[3];

        // ---- phase B: in-warp pointwise for (bt, uo)
        {
            float si = sig_fast(gi);
            float sf = sig_fast(gf);
            float tg = tanh_fast(gc);
            float so = sig_fast(go);
            c = sf * c + si * tg;
            float h = so * tanh_fast(c);
            hx[nbuf][bt][uo] = __float2half_rn(h);

            bool wr = dir ? (t == 0) : (t == mylen - 1);
            if (wr)
                g_h1last[(bbase + bt) * 128 + dir * HQ + uo] = h;
        }
#pragma unroll
        for (int q = 0; q < 4; ++q) ldc[q] = ldn[q];
        __syncthreads();
    }
}

// =====================================================================
// Final head: FB=4 batches per block; class range split in 2.
// =====================================================================
__global__ void __launch_bounds__(256)
final_kernel(const float* __restrict__ Wout, const float* __restrict__ bout,
             float* __restrict__ out)
{
    const int bbase = blockIdx.x * FB;
    const int chalf = blockIdx.y;
    __shared__ float hs[FB][128];
    for (int i = threadIdx.x; i < FB * 128; i += 256)
        hs[i >> 7][i & 127] = g_h1last[bbase * 128 + i];
    __syncthreads();

    const int cbeg = chalf * 549;
    const int cend = cbeg + 549;
    for (int cl = cbeg + threadIdx.x; cl < cend; cl += 256) {
        const float4* wv = reinterpret_cast<const float4*>(Wout + (size_t)cl * 128);
        float a[FB];
#pragma unroll
        for (int b = 0; b < FB; ++b) a[b] = bout[cl];
#pragma unroll
        for (int k = 0; k < 32; ++k) {
            float4 v = wv[k];
#pragma unroll
            for (int b = 0; b < FB; ++b) {
                a[b] += hs[b][4 * k + 0] * v.x + hs[b][4 * k + 1] * v.y
                      + hs[b][4 * k + 2] * v.z + hs[b][4 * k + 3] * v.w;
            }
        }
#pragma unroll
        for (int b = 0; b < FB; ++b)
            out[(size_t)(bbase + b) * NCLS + cl] = a[b];
    }
}

// =====================================================================
extern "C" void kernel_launch(void* const* d_in, const int* in_sizes, int n_in,
                              void* d_out, int out_size)
{
    const float* x     = (const float*)d_in[0];
    const int*   lens  = (const int*)  d_in[1];
    const float* Wih0f = (const float*)d_in[2];
    const float* Whh0f = (const float*)d_in[3];
    const float* bih0f = (const float*)d_in[4];
    const float* bhh0f = (const float*)d_in[5];
    const float* Wih0b = (const float*)d_in[6];
    const float* Whh0b = (const float*)d_in[7];
    const float* bih0b = (const float*)d_in[8];
    const float* bhh0b = (const float*)d_in[9];
    const float* Wih1f = (const float*)d_in[10];
    const float* Whh1f = (const float*)d_in[11];
    const float* bih1f = (const float*)d_in[12];
    const float* bhh1f = (const float*)d_in[13];
    const float* Wih1b = (const float*)d_in[14];
    const float* Whh1b = (const float*)d_in[15];
    const float* bih1b = (const float*)d_in[16];
    const float* bhh1b = (const float*)d_in[17];
    const float* Wout  = (const float*)d_in[18];
    const float* bout  = (const float*)d_in[19];

    static bool attr_set = false;
    if (!attr_set) {
        cudaFuncSetAttribute(gates1_gemm_kernel,
                             cudaFuncAttributeMaxDynamicSharedMemorySize, GEMM_SMEM);
        attr_set = true;
    }

    lstm_l0_kernel<<<256, 256>>>(x, lens,
                                 Wih0f, Whh0f, bih0f, bhh0f,
                                 Wih0b, Whh0b, bih0b, bhh0b);

    dim3 gg(TQ / GM_ROWS, BQ, 2);
    gates1_gemm_kernel<<<gg, 256, GEMM_SMEM>>>(lens, Wih1f, Wih1b,
                                               bih1f, bhh1f, bih1b, bhh1b);

    lstm_l1_kernel<<<256, 256>>>(lens, Whh1f, Whh1b);

    dim3 gf(BQ / FB, 2);
    final_kernel<<<gf, 256>>>(Wout, bout, (float*)d_out);
}

// round 17
// speedup vs baseline: 1.1025x; 1.1025x over previous
#include <cuda_runtime.h>
#include <cuda_fp16.h>
#include <math.h>

#define BQ   512
#define TQ   1024
#define DQ   4
#define HQ   64
#define G4   256          // 4*H
#define NB   4            // batches per recurrent block (2 blocks/SM, paired)
#define NCLS 1098
#define FB   4            // batches per final-head block

#define HXH_STRIDE 88     // halves; conflict-free B-frag LDS (audited)
#define GP_STRIDE  6      // gpre[gate][batch] stride (float2-aligned)

// ---------------- scratch (static device allocations only) ----------------
__device__ float  g_g1[2][(size_t)BQ * TQ * G4];  // layer-1 gate preactivations per dir
__device__ __half g_h0[(size_t)BQ * TQ * 128];    // layer-0 bidir output (fp16)
__device__ float  g_h1last[BQ * 128];             // gathered last timestep of layer 1
__device__ __half g_WoutH[(size_t)NCLS * 128];    // fp16 copy of W_out

// ---------------- helpers ----------------
__device__ __forceinline__ float tanh_fast(float x) {
    float y; asm("tanh.approx.f32 %0,%1;" : "=f"(y) : "f"(x)); return y;
}
__device__ __forceinline__ float sig_fast(float x) {
    return fmaf(0.5f, tanh_fast(0.5f * x), 0.5f);
}
__device__ __forceinline__ unsigned pack_h2(float lo, float hi) {
    __half2 h = __floats2half2_rn(lo, hi);
    return *reinterpret_cast<unsigned*>(&h);
}
// fp16 MMA, fp32 accumulate
__device__ __forceinline__ void mma_f16(float* c, const unsigned* a, unsigned b0, unsigned b1) {
    asm volatile(
        "mma.sync.aligned.m16n8k16.row.col.f32.f16.f16.f32 "
        "{%0,%1,%2,%3},{%4,%5,%6,%7},{%8,%9},{%0,%1,%2,%3};"
        : "+f"(c[0]), "+f"(c[1]), "+f"(c[2]), "+f"(c[3])
        : "r"(a[0]), "r"(a[1]), "r"(a[2]), "r"(a[3]), "r"(b0), "r"(b1));
}

// block (0..255) -> sorted group id: pairs wave-1 co-resident blocks
// (bid, bid+148) with (long, short) sequence groups.
__device__ __forceinline__ void block_to_group(int bid, int& dir, int& xb) {
    int j = (bid < 148) ? bid : (403 - bid);
    dir = j & 1;
    xb  = j >> 1;
}

// =====================================================================
// Layer 0: bidirectional LSTM; fp16 tensor-core matvec (K=64, Whh only)
// + exchange phase B with SCALAR x-projection/bias (idle FMA pipe).
// 8 HMMA/warp/step (was 10). Per-thread W_ih rows + bias in registers;
// x staged in float4 smem, double-buffered.
// =====================================================================
__global__ void __launch_bounds__(256, 2)
lstm_l0_kernel(const float* __restrict__ x, const int* __restrict__ lens,
               const float* __restrict__ WihF, const float* __restrict__ WhhF,
               const float* __restrict__ bihF, const float* __restrict__ bhhF,
               const float* __restrict__ WihB, const float* __restrict__ WhhB,
               const float* __restrict__ bihB, const float* __restrict__ bhhB)
{
    int dir, xb;
    block_to_group(blockIdx.x, dir, xb);
    const int bbase = xb * NB;
    const int tid  = threadIdx.x;
    const int w    = tid >> 5;
    const int lane = tid & 31;
    const int gid  = lane >> 2;               // 0..7
    const int tig  = lane & 3;                // 0..3

    const float* Wih = dir ? WihB : WihF;
    const float* Whh = dir ? WhhB : WhhF;
    const float* bih = dir ? bihB : bihF;
    const float* bhh = dir ? bhhB : bhhF;

    // ---- A fragments (fp16), natural gate order, K = 64 (Whh only)
    unsigned afr[2][4][4];
#pragma unroll
    for (int mt = 0; mt < 2; ++mt) {
#pragma unroll
        for (int kc = 0; kc < 4; ++kc) {
#pragma unroll
            for (int e = 0; e < 4; ++e) {
                int g  = w * 32 + mt * 16 + gid + ((e & 1) ? 8 : 0);
                int kb = kc * 16 + 2 * tig + ((e & 2) ? 8 : 0);
                afr[mt][kc][e] = pack_h2(Whh[g * HQ + kb], Whh[g * HQ + kb + 1]);
            }
        }
    }

    // ---- per-thread x-projection weights + bias for phase-B role
    const int pb_b = tid >> 6, pb_j = tid & 63;
    float wihr[4][4], bsum[4];
#pragma unroll
    for (int q = 0; q < 4; ++q) {
        int gq = q * 64 + pb_j;
#pragma unroll
        for (int k = 0; k < 4; ++k) wihr[q][k] = Wih[gq * DQ + k];
        bsum[q] = bih[gq] + bhh[gq];
    }

    __shared__ __half hx[2][8][HXH_STRIDE];
    __shared__ float  gpre[G4 * GP_STRIDE];
    __shared__ float4 xs[2][NB];
    __shared__ int    lsh[NB];

    if (tid < NB) lsh[tid] = lens[bbase + tid];
    for (int i = tid; i < 2 * 8 * HXH_STRIDE; i += 256)
        (&hx[0][0][0])[i] = __float2half(0.0f);
    __syncthreads();

    const int maxlen = lsh[0];                // lens sorted descending
    float c = 0.0f;

    if (tid < NB) {
        int len = lsh[tid];
        int tt  = dir ? (len - 1) : 0;
        xs[0][tid] = reinterpret_cast<const float4*>(x)[(size_t)(bbase + tid) * TQ + tt];
    }
    __syncthreads();

    for (int t = 0; t < maxlen; ++t) {
        const int buf = t & 1, nbuf = buf ^ 1;

        // prefetch x(t+1) (overlaps MMA)
        float4 xn = make_float4(0.f, 0.f, 0.f, 0.f);
        if (tid < NB) {
            int tn  = (t + 1 < maxlen) ? (t + 1) : t;
            int len = lsh[tid];
            int tt  = dir ? ((tn < len) ? (len - 1 - tn) : tn) : tn;
            xn = reinterpret_cast<const float4*>(x)[(size_t)(bbase + tid) * TQ + tt];
        }

        // ---- phase A: fp16 tensor-core matvec (4 K-chunks, 2 tiles)
        const __half* hxb = &hx[buf][gid][0];
        float a0[4] = {0.f, 0.f, 0.f, 0.f}, a1[4] = {0.f, 0.f, 0.f, 0.f};
#pragma unroll
        for (int kc = 0; kc < 4; ++kc) {
            unsigned p = *reinterpret_cast<const unsigned*>(&hxb[kc * 16 + 2 * tig]);
            unsigned q = *reinterpret_cast<const unsigned*>(&hxb[kc * 16 + 2 * tig + 8]);
            mma_f16(a0, afr[0][kc], p, q);
            mma_f16(a1, afr[1][kc], p, q);
        }
        if (tig < 2) {
            int g0 = w * 32 + gid;
            *reinterpret_cast<float2*>(&gpre[g0 * GP_STRIDE + 2 * tig]) =
                make_float2(a0[0], a0[1]);
            *reinterpret_cast<float2*>(&gpre[(g0 + 8) * GP_STRIDE + 2 * tig]) =
                make_float2(a0[2], a0[3]);
            *reinterpret_cast<float2*>(&gpre[(g0 + 16) * GP_STRIDE + 2 * tig]) =
                make_float2(a1[0], a1[1]);
            *reinterpret_cast<float2*>(&gpre[(g0 + 24) * GP_STRIDE + 2 * tig]) =
                make_float2(a1[2], a1[3]);
        }
        __syncthreads();

        // ---- phase B: pointwise cell update for (pb_b, pb_j);
        //      x-projection + bias computed here in fp32 (idle FMA pipe)
        {
            float4 xv = xs[buf][pb_b];
            float xp[4];
#pragma unroll
            for (int q = 0; q < 4; ++q)
                xp[q] = bsum[q] + wihr[q][0] * xv.x + wihr[q][1] * xv.y
                                + wihr[q][2] * xv.z + wihr[q][3] * xv.w;

            float gi = gpre[(pb_j)       * GP_STRIDE + pb_b] + xp[0];
            float gf = gpre[(64  + pb_j) * GP_STRIDE + pb_b] + xp[1];
            float gc = gpre[(128 + pb_j) * GP_STRIDE + pb_b] + xp[2];
            float go = gpre[(192 + pb_j) * GP_STRIDE + pb_b] + xp[3];
            float si = sig_fast(gi);
            float sf = sig_fast(gf);
            float tg = tanh_fast(gc);
            float so = sig_fast(go);
            c = sf * c + si * tg;
            float h = so * tanh_fast(c);
            __half hh = __float2half_rn(h);
            hx[nbuf][pb_b][pb_j] = hh;

            int len = lsh[pb_b];
            int ts  = dir ? ((t < len) ? (len - 1 - t) : t) : t;
            g_h0[((size_t)(bbase + pb_b) * TQ + ts) * 128 + dir * HQ + pb_j] = hh;
        }
        if (tid < NB) xs[nbuf][tid] = xn;
        __syncthreads();
    }
}

// =====================================================================
// Layer-1 gate GEMM on fp16 tensor cores (R13, unchanged).
// =====================================================================
#define GM_ROWS   64
#define ASH_STRIDE 136
#define WSH_STRIDE 136
#define GEMM_SMEM ((GM_ROWS * ASH_STRIDE + G4 * WSH_STRIDE) * 2)   // 87040 B

__global__ void __launch_bounds__(256, 2)
gates1_gemm_kernel(const int* __restrict__ lens,
                   const float* __restrict__ WihF, const float* __restrict__ WihB,
                   const float* __restrict__ bihF, const float* __restrict__ bhhF,
                   const float* __restrict__ bihB, const float* __restrict__ bhhB)
{
    const int tile  = blockIdx.x;
    const int b     = blockIdx.y;
    const int dir   = blockIdx.z;
    const int tbase = tile * GM_ROWS;

    const int len = lens[b];
    if (tbase >= len) return;

    extern __shared__ __half smh[];
    __half* As = smh;
    __half* Ws = smh + GM_ROWS * ASH_STRIDE;

    const int tid  = threadIdx.x;
    const int lane = tid & 31;
    const int w    = tid >> 5;
    const int wr   = w & 3;
    const int wc   = w >> 2;
    const int gid  = lane >> 2;
    const int tig  = lane & 3;

    const float* Wih = dir ? WihB : WihF;
    const float* bih = dir ? bihB : bihF;
    const float* bhh = dir ? bhhB : bhhF;

    float acc[16][4];
#pragma unroll
    for (int nt = 0; nt < 16; ++nt) {
        int col0 = wc * 128 + nt * 8 + 2 * tig;
        float bv0 = bih[col0]     + bhh[col0];
        float bv1 = bih[col0 + 1] + bhh[col0 + 1];
        acc[nt][0] = bv0; acc[nt][1] = bv1;
        acc[nt][2] = bv0; acc[nt][3] = bv1;
    }

    const __half* h0b = g_h0 + (size_t)b * TQ * 128;
#pragma unroll
    for (int i = 0; i < 4; ++i) {
        int idx = tid + 256 * i;
        int r   = idx >> 4, kq = idx & 15;
        int srow = tbase + r;
        if (dir) srow = (srow < len) ? (len - 1 - srow) : srow;
        uint4 v = *reinterpret_cast<const uint4*>(h0b + (size_t)srow * 128 + 8 * kq);
        *reinterpret_cast<uint4*>(&As[r * ASH_STRIDE + 8 * kq]) = v;
    }

#pragma unroll
    for (int i = 0; i < 32; ++i) {
        int idx = tid + 256 * i;
        int n   = idx >> 5, kq = idx & 31;
        float4 v = *reinterpret_cast<const float4*>(Wih + (size_t)n * 128 + 4 * kq);
        __half2 lo = __floats2half2_rn(v.x, v.y);
        __half2 hi = __floats2half2_rn(v.z, v.w);
        *reinterpret_cast<__half2*>(&Ws[n * WSH_STRIDE + 4 * kq])     = lo;
        *reinterpret_cast<__half2*>(&Ws[n * WSH_STRIDE + 4 * kq + 2]) = hi;
    }
    __syncthreads();

    const int r0 = wr * 16 + gid;

#pragma unroll
    for (int kc = 0; kc < 8; ++kc) {
        const int kl = kc * 16;
        unsigned a[4];
        a[0] = *reinterpret_cast<const unsigned*>(&As[r0 * ASH_STRIDE + kl + 2 * tig]);
        a[1] = *reinterpret_cast<const unsigned*>(&As[(r0 + 8) * ASH_STRIDE + kl + 2 * tig]);
        a[2] = *reinterpret_cast<const unsigned*>(&As[r0 * ASH_STRIDE + kl + 2 * tig + 8]);
        a[3] = *reinterpret_cast<const unsigned*>(&As[(r0 + 8) * ASH_STRIDE + kl + 2 * tig + 8]);
#pragma unroll
        for (int nt = 0; nt < 16; ++nt) {
            int n = wc * 128 + nt * 8 + gid;
            unsigned b0 = *reinterpret_cast<const unsigned*>(&Ws[n * WSH_STRIDE + kl + 2 * tig]);
            unsigned b1 = *reinterpret_cast<const unsigned*>(&Ws[n * WSH_STRIDE + kl + 2 * tig + 8]);
            mma_f16(acc[nt], a, b0, b1);
        }
    }

    float* outp = g_g1[dir] + ((size_t)b * TQ + tbase) * G4;
#pragma unroll
    for (int nt = 0; nt < 16; ++nt) {
        int col0 = wc * 128 + nt * 8 + 2 * tig;
        *reinterpret_cast<float2*>(outp + (size_t)r0 * G4 + col0) =
            make_float2(acc[nt][0], acc[nt][1]);
        *reinterpret_cast<float2*>(outp + (size_t)(r0 + 8) * G4 + col0) =
            make_float2(acc[nt][2], acc[nt][3]);
    }
}

// =====================================================================
// Layer 1: recurrent over precomputed gates; fp16 MMA (K=64) + exchange
// phase B with per-thread preact streams. (R13, unchanged)
// =====================================================================
__global__ void __launch_bounds__(256, 2)
lstm_l1_kernel(const int* __restrict__ lens,
               const float* __restrict__ WhhF, const float* __restrict__ WhhB)
{
    int dir, xb;
    block_to_group(blockIdx.x, dir, xb);
    const int bbase = xb * NB;
    const int tid  = threadIdx.x;
    const int w    = tid >> 5;
    const int lane = tid & 31;
    const int gid  = lane >> 2;
    const int tig  = lane & 3;

    const float* Whh = dir ? WhhB : WhhF;
    const float* gin = g_g1[dir];

    // ---- A fragments (fp16), natural gate order, K = 64
    unsigned afr[2][4][4];
#pragma unroll
    for (int mt = 0; mt < 2; ++mt) {
#pragma unroll
        for (int kc = 0; kc < 4; ++kc) {
#pragma unroll
            for (int e = 0; e < 4; ++e) {
                int g  = w * 32 + mt * 16 + gid + ((e & 1) ? 8 : 0);
                int kb = kc * 16 + 2 * tig + ((e & 2) ? 8 : 0);
                afr[mt][kc][e] = pack_h2(Whh[g * HQ + kb], Whh[g * HQ + kb + 1]);
            }
        }
    }

    __shared__ __half hx[2][8][HXH_STRIDE];
    __shared__ float  gpre[G4 * GP_STRIDE];
    __shared__ int    lsh[NB];

    const int pb_b = tid >> 6, pb_j = tid & 63;
    if (tid < NB) lsh[tid] = lens[bbase + tid];
    for (int i = tid; i < 2 * 8 * HXH_STRIDE; i += 256)
        (&hx[0][0][0])[i] = __float2half(0.0f);
    float c = 0.0f;
    __syncthreads();

    const int maxlen = lsh[0];

    // per-thread preact stream for phase-B role (pb_b, pb_j)
    const float* gsrc = gin + (size_t)(bbase + pb_b) * TQ * G4 + pb_j;

    float ldc[4];
#pragma unroll
    for (int q = 0; q < 4; ++q) ldc[q] = gsrc[q * 64];

    for (int t = 0; t < maxlen; ++t) {
        const int buf = t & 1, nbuf = buf ^ 1;

        // prefetch next-step preacts (overlaps MMA)
        float ldn[4];
        const int tn = (t + 1 < maxlen) ? (t + 1) : t;
#pragma unroll
        for (int q = 0; q < 4; ++q) ldn[q] = gsrc[(size_t)tn * G4 + q * 64];

        // ---- phase A: fp16 tensor-core matvec (4 K-chunks, 2 tiles)
        const __half* hxb = &hx[buf][gid][0];
        float a0[4] = {0.f, 0.f, 0.f, 0.f}, a1[4] = {0.f, 0.f, 0.f, 0.f};
#pragma unroll
        for (int kc = 0; kc < 4; ++kc) {
            unsigned p = *reinterpret_cast<const unsigned*>(&hxb[kc * 16 + 2 * tig]);
            unsigned q = *reinterpret_cast<const unsigned*>(&hxb[kc * 16 + 2 * tig + 8]);
            mma_f16(a0, afr[0][kc], p, q);
            mma_f16(a1, afr[1][kc], p, q);
        }
        if (tig < 2) {
            int g0 = w * 32 + gid;
            *reinterpret_cast<float2*>(&gpre[g0 * GP_STRIDE + 2 * tig]) =
                make_float2(a0[0], a0[1]);
            *reinterpret_cast<float2*>(&gpre[(g0 + 8) * GP_STRIDE + 2 * tig]) =
                make_float2(a0[2], a0[3]);
            *reinterpret_cast<float2*>(&gpre[(g0 + 16) * GP_STRIDE + 2 * tig]) =
                make_float2(a1[0], a1[1]);
            *reinterpret_cast<float2*>(&gpre[(g0 + 24) * GP_STRIDE + 2 * tig]) =
                make_float2(a1[2], a1[3]);
        }
        __syncthreads();

        // ---- phase B: pointwise for (pb_b, pb_j), preacts added here
        {
            float gi = gpre[(pb_j)       * GP_STRIDE + pb_b] + ldc[0];
            float gf = gpre[(64  + pb_j) * GP_STRIDE + pb_b] + ldc[1];
            float gc = gpre[(128 + pb_j) * GP_STRIDE + pb_b] + ldc[2];
            float go = gpre[(192 + pb_j) * GP_STRIDE + pb_b] + ldc[3];
            float si = sig_fast(gi);
            float sf = sig_fast(gf);
            float tg = tanh_fast(gc);
            float so = sig_fast(go);
            c = sf * c + si * tg;
            float h = so * tanh_fast(c);
            hx[nbuf][pb_b][pb_j] = __float2half_rn(h);

            int  len = lsh[pb_b];
            bool wr  = dir ? (t == 0) : (t == len - 1);
            if (wr)
                g_h1last[(bbase + pb_b) * 128 + dir * HQ + pb_j] = h;
        }
#pragma unroll
        for (int q = 0; q < 4; ++q) ldc[q] = ldn[q];
        __syncthreads();
    }
}

// =====================================================================
// W_out fp32 -> fp16 conversion (one-shot, tiny)
// =====================================================================
__global__ void convert_wout_kernel(const float* __restrict__ Wout)
{
    int idx = blockIdx.x * 256 + threadIdx.x;       // float4 slots
    if (idx < NCLS * 32) {
        float4 v = reinterpret_cast<const float4*>(Wout)[idx];
        __half2 lo = __floats2half2_rn(v.x, v.y);
        __half2 hi = __floats2half2_rn(v.z, v.w);
        *reinterpret_cast<__half2*>(&g_WoutH[idx * 4])     = lo;
        *reinterpret_cast<__half2*>(&g_WoutH[idx * 4 + 2]) = hi;
    }
}

// =====================================================================
// Final head: FB=4 batches per block; class range split in 2; fp16 W_out.
// =====================================================================
__global__ void __launch_bounds__(256)
final_kernel(const float* __restrict__ bout, float* __restrict__ out)
{
    const int bbase = blockIdx.x * FB;
    const int chalf = blockIdx.y;
    __shared__ float hs[FB][128];
    for (int i = threadIdx.x; i < FB * 128; i += 256)
        hs[i >> 7][i & 127] = g_h1last[bbase * 128 + i];
    __syncthreads();

    const int cbeg = chalf * 549;
    const int cend = cbeg + 549;
    for (int cl = cbeg + threadIdx.x; cl < cend; cl += 256) {
        const uint4* wv = reinterpret_cast<const uint4*>(g_WoutH + (size_t)cl * 128);
        float a[FB];
#pragma unroll
        for (int b = 0; b < FB; ++b) a[b] = bout[cl];
#pragma unroll
        for (int k = 0; k < 16; ++k) {
            uint4 v = wv[k];
            const __half2* h2 = reinterpret_cast<const __half2*>(&v);
#pragma unroll
            for (int j = 0; j < 4; ++j) {
                float2 f = __half22float2(h2[j]);
#pragma unroll
                for (int b = 0; b < FB; ++b) {
                    a[b] += hs[b][8 * k + 2 * j] * f.x
                          + hs[b][8 * k + 2 * j + 1] * f.y;
                }
            }
        }
#pragma unroll
        for (int b = 0; b < FB; ++b)
            out[(size_t)(bbase + b) * NCLS + cl] = a[b];
    }
}

// =====================================================================
extern "C" void kernel_launch(void* const* d_in, const int* in_sizes, int n_in,
                              void* d_out, int out_size)
{
    const float* x     = (const float*)d_in[0];
    const int*   lens  = (const int*)  d_in[1];
    const float* Wih0f = (const float*)d_in[2];
    const float* Whh0f = (const float*)d_in[3];
    const float* bih0f = (const float*)d_in[4];
    const float* bhh0f = (const float*)d_in[5];
    const float* Wih0b = (const float*)d_in[6];
    const float* Whh0b = (const float*)d_in[7];
    const float* bih0b = (const float*)d_in[8];
    const float* bhh0b = (const float*)d_in[9];
    const float* Wih1f = (const float*)d_in[10];
    const float* Whh1f = (const float*)d_in[11];
    const float* bih1f = (const float*)d_in[12];
    const float* bhh1f = (const float*)d_in[13];
    const float* Wih1b = (const float*)d_in[14];
    const float* Whh1b = (const float*)d_in[15];
    const float* bih1b = (const float*)d_in[16];
    const float* bhh1b = (const float*)d_in[17];
    const float* Wout  = (const float*)d_in[18];
    const float* bout  = (const float*)d_in[19];

    static bool attr_set = false;
    if (!attr_set) {
        cudaFuncSetAttribute(gates1_gemm_kernel,
                             cudaFuncAttributeMaxDynamicSharedMemorySize, GEMM_SMEM);
        attr_set = true;
    }

    convert_wout_kernel<<<(NCLS * 32 + 255) / 256, 256>>>(Wout);

    lstm_l0_kernel<<<256, 256>>>(x, lens,
                                 Wih0f, Whh0f, bih0f, bhh0f,
                                 Wih0b, Whh0b, bih0b, bhh0b);

    dim3 gg(TQ / GM_ROWS, BQ, 2);
    gates1_gemm_kernel<<<gg, 256, GEMM_SMEM>>>(lens, Wih1f, Wih1b,
                                               bih1f, bhh1f, bih1b, bhh1b);

    lstm_l1_kernel<<<256, 256>>>(lens, Whh1f, Whh1b);

    dim3 gf(BQ / FB, 2);
    final_kernel<<<gf, 256>>>(bout, (float*)d_out);
}